// round 12
// baseline (speedup 1.0000x reference)
#include <cuda_runtime.h>
#include <cuda_fp16.h>
#include <cstdint>

#define NB   32
#define HWD  128
#define CONDD 256
#define HIDD 4608
#define NPARAM 9216

// Scratch (device globals: allocation-free rule)
__device__ __align__(16) __half g_hh[NB * HIDD];
#define WB_ROW   296
#define WB_ELEMS (32 * WB_ROW)              // 9472 per sample
__device__ __align__(16) __half g_wb[NB * WB_ELEMS];
// x fp16, layout [b][c4 0..3][y][x][cin8]  (32 MB)
__device__ __align__(16) __half g_xh[(size_t)NB * 4 * HWD * HWD * 8];

__device__ __forceinline__ uint32_t smem_to_u32(const void* p) {
    uint32_t a;
    asm("{ .reg .u64 t; cvta.to.shared.u64 t, %1; cvt.u32.u64 %0, t; }"
        : "=r"(a) : "l"(p));
    return a;
}

// ---------------------------------------------------------------------------
// warp-mma helpers
// ---------------------------------------------------------------------------
__device__ __forceinline__ void ldsm_x4(uint32_t r[4], uint32_t addr) {
    asm volatile("ldmatrix.sync.aligned.m8n8.x4.shared.b16 {%0,%1,%2,%3}, [%4];"
        : "=r"(r[0]), "=r"(r[1]), "=r"(r[2]), "=r"(r[3]) : "r"(addr));
}
__device__ __forceinline__ void mma_f16(float d[4], const uint32_t a[4],
                                        uint32_t b0, uint32_t b1) {
    asm volatile(
        "mma.sync.aligned.m16n8k16.row.col.f32.f16.f16.f32 "
        "{%0,%1,%2,%3}, {%4,%5,%6,%7}, {%8,%9}, {%0,%1,%2,%3};"
        : "+f"(d[0]), "+f"(d[1]), "+f"(d[2]), "+f"(d[3])
        : "r"(a[0]), "r"(a[1]), "r"(a[2]), "r"(a[3]), "r"(b0), "r"(b1));
}

// ---------------------------------------------------------------------------
// Kernel 0: x fp32 [b][cin][y][x] -> g_xh fp16 [b][c4][y][x][cin8]
// ---------------------------------------------------------------------------
__global__ void xprep_kernel(const float* __restrict__ x) {
    int b = blockIdx.y, y = blockIdx.x, t = threadIdx.x;   // 512 threads
    int c4 = t >> 7;
    int xx = t & 127;
    float v[8];
#pragma unroll
    for (int i = 0; i < 8; i++)
        v[i] = x[(((size_t)b * 32 + c4 * 8 + i) * HWD + y) * HWD + xx];
    __half2 h[4];
#pragma unroll
    for (int i = 0; i < 4; i++)
        h[i] = __floats2half2_rn(v[2 * i], v[2 * i + 1]);
    uint4 o = make_uint4(*(uint32_t*)&h[0], *(uint32_t*)&h[1],
                         *(uint32_t*)&h[2], *(uint32_t*)&h[3]);
    *(uint4*)(g_xh + ((((size_t)b * 4 + c4) * HWD + y) * HWD + xx) * 8) = o;
}

// ---------------------------------------------------------------------------
// Kernel 1: h = relu(cond @ W1^T + b1) -> g_hh fp16 [b][hid]
// ---------------------------------------------------------------------------
__global__ void mlp1_kernel(const float* __restrict__ cond,
                            const float* __restrict__ W1,
                            const float* __restrict__ b1) {
    int idx = blockIdx.x * blockDim.x + threadIdx.x;
    int hid = idx >> 5;
    int b   = idx & 31;
    const float4* c4 = (const float4*)(cond + b * CONDD);
    const float4* w4 = (const float4*)(W1 + (size_t)hid * CONDD);
    float acc = b1[hid];
#pragma unroll 8
    for (int i = 0; i < CONDD / 4; i++) {
        float4 cv = c4[i]; float4 wv = w4[i];
        acc += cv.x * wv.x + cv.y * wv.y + cv.z * wv.z + cv.w * wv.w;
    }
    g_hh[b * HIDD + hid] = __float2half_rn(fmaxf(acc, 0.0f));
}

// ---------------------------------------------------------------------------
// Kernel 2: tensor-core gemm2, double-buffered smem pipeline.
// CTA = 32 p-rows, 128 threads (4 warps = mh x nw), grid 288.
// ---------------------------------------------------------------------------
#define GP 32
#define GK 128
#define TST 272
#define SB_OFF 0                 // B tile: 32 rows
#define SA_OFF (32 * TST)        // A tile: 32 rows
#define G2_BUF (64 * TST)        // 17408 B per buffer
#define G2_SMEM (2 * G2_BUF)     // 34816 B

__global__ void __launch_bounds__(128, 2)
gemm2_kernel(const float* __restrict__ W2, const float* __restrict__ b2) {
    __shared__ __align__(16) unsigned char sm[G2_SMEM];

    int t = threadIdx.x, lane = t & 31, w = t >> 5;
    int pbase = blockIdx.x * GP;
    const int NCH = HIDD / GK;       // 36 chunks

    // per-thread load slots
    int brow = t >> 2;
    int bf4  = t & 3;
    const float4* W24 = (const float4*)(W2 + (size_t)(pbase + brow) * HIDD);
    int arow[4], ac[4];
#pragma unroll
    for (int i = 0; i < 4; i++) {
        int j = t + 128 * i; arow[i] = j >> 4; ac[i] = j & 15;
    }

    uint32_t SMB = smem_to_u32(sm);

    float4 rw[8]; uint4 rh[4];
    auto load_chunk = [&](int kc) {
        int ko = kc * 32;
#pragma unroll
        for (int i = 0; i < 8; i++) rw[i] = W24[ko + bf4 + 4 * i];
        int kh = kc * GK;
#pragma unroll
        for (int i = 0; i < 4; i++)
            rh[i] = *(const uint4*)(g_hh + (size_t)arow[i] * HIDD + kh + ac[i] * 8);
    };
    auto store_tiles = [&](uint32_t bofs) {
#pragma unroll
        for (int i = 0; i < 8; i++) {
            __half2 h0 = __floats2half2_rn(rw[i].x, rw[i].y);
            __half2 h1 = __floats2half2_rn(rw[i].z, rw[i].w);
            uint32_t u0 = *(uint32_t*)&h0, u1 = *(uint32_t*)&h1;
            uint32_t addr = SMB + bofs + SB_OFF + (uint32_t)brow * TST +
                            (uint32_t)(bf4 + 4 * i) * 8u;
            asm volatile("st.shared.v2.b32 [%0], {%1, %2};"
                         :: "r"(addr), "r"(u0), "r"(u1) : "memory");
        }
#pragma unroll
        for (int i = 0; i < 4; i++) {
            uint32_t a0 = SMB + bofs + SA_OFF + (uint32_t)arow[i] * TST + ac[i] * 16u;
            asm volatile("st.shared.v4.b32 [%0], {%1, %2, %3, %4};"
                :: "r"(a0), "r"(rh[i].x), "r"(rh[i].y), "r"(rh[i].z), "r"(rh[i].w) : "memory");
        }
    };

    int mh = w & 1;
    int nw = w >> 1;
    uint32_t Abase = SA_OFF +
        (uint32_t)(mh * 16 + (lane & 15)) * TST + (uint32_t)(lane >> 4) * 16u;
    uint32_t Bbase = SB_OFF +
        (uint32_t)(nw * 16 + (((lane >> 4) & 1) * 8) + (lane & 7)) * TST +
        (uint32_t)((lane >> 3) & 1) * 16u;

    float d0[4] = {0, 0, 0, 0}, d1[4] = {0, 0, 0, 0};

    // prologue: chunk0 -> buf0, prefetch chunk1
    load_chunk(0);
    store_tiles(0);
    load_chunk(1);
    __syncthreads();

    for (int kc = 0; kc < NCH; kc++) {
        uint32_t cur = (uint32_t)(kc & 1) * G2_BUF;
        if (kc + 1 < NCH) {
            store_tiles(G2_BUF - cur);          // buf[(kc+1)&1]
            if (kc + 2 < NCH) load_chunk(kc + 2);
        }
        __syncthreads();
#pragma unroll
        for (int ks = 0; ks < 8; ks++) {
            uint32_t A[4], B[4];
            ldsm_x4(A, SMB + cur + Abase + (uint32_t)ks * 32u);
            ldsm_x4(B, SMB + cur + Bbase + (uint32_t)ks * 32u);
            mma_f16(d0, A, B[0], B[1]);
            mma_f16(d1, A, B[2], B[3]);
        }
        __syncthreads();
    }

    // ---- fused epilogue: bias, p -> (co, k) scatter, fp16 store ----
    int g  = lane >> 2;
    int tg = lane & 3;
#pragma unroll
    for (int j = 0; j < 2; j++) {
        const float* dj = (j == 0) ? d0 : d1;
#pragma unroll
        for (int c = 0; c < 2; c++) {
            int p = pbase + nw * 16 + j * 8 + tg * 2 + c;
            float bias = b2[p];
            int co = p / 288;
            int r  = p - co * 288;
            int cin = r / 9;
            int rr  = r - cin * 9;
            int k   = rr * 32 + cin;
            int b0 = mh * 16 + g;
            g_wb[(size_t)b0 * WB_ELEMS + co * WB_ROW + k] =
                __float2half_rn(dj[c] + bias);
            g_wb[(size_t)(b0 + 8) * WB_ELEMS + co * WB_ROW + k] =
                __float2half_rn(dj[2 + c] + bias);
        }
    }
}

// ---------------------------------------------------------------------------
// Kernel 3: warp-mma conv, fp16. CTA = (b, 8 out rows, FULL 128 cols),
// 512 threads = 16 warps: warp = (yw 0..7, x-half 0..1 of 64 cols) =
// 4 mtiles x 4 ntiles. Per (q,h): 6 ldsm (A0..A3, B0, B1) -> 16 mma.
// ---------------------------------------------------------------------------
#define XT_XS 40
#define XT_COLS 130
#define XT_YS (XT_COLS * XT_XS)       // 5200 elems per y row
#define XT_ROWS 10                    // 8 out rows + halo
#define XT_BYTES (XT_ROWS * XT_YS * 2)   // 104000 B
#define SB_ROWB (WB_ROW * 2)          // 592 B per co row
#define SB_BYTES (32 * SB_ROWB)       // 18944 B
#define CONV_SMEM (XT_BYTES + SB_BYTES)  // 122944 B

__global__ void __launch_bounds__(512, 1)
conv_kernel(float* __restrict__ out) {
    extern __shared__ unsigned char smem[];
    uint4* s_b4 = (uint4*)(smem + XT_BYTES);

    int t = threadIdx.x, lane = t & 31, w = t >> 5;
    int b  = blockIdx.y;
    int y0 = blockIdx.x * 8;

    {
        const uint4* src = (const uint4*)(g_wb + (size_t)b * WB_ELEMS);
        for (int i = t; i < SB_BYTES / 16; i += 512) s_b4[i] = src[i];
    }
    {
        const __half* xsrc = g_xh + (size_t)b * (4 * HWD * HWD * 8);
        for (int idx = t; idx < XT_ROWS * XT_COLS * 4; idx += 512) {
            int row = idx >> 2, c4 = idx & 3;
            int y  = row / XT_COLS, xx = row - y * XT_COLS;
            int gy = y0 - 1 + y, gx = xx - 1;
            uint4 v = make_uint4(0, 0, 0, 0);
            if (gy >= 0 && gy < HWD && gx >= 0 && gx < HWD)
                v = *(const uint4*)(xsrc + (((size_t)c4 * HWD + gy) * HWD + gx) * 8);
            *(uint4*)(smem + (size_t)(y * XT_YS + xx * XT_XS) * 2 + c4 * 16) = v;
        }
    }
    __syncthreads();

    uint32_t XB = smem_to_u32(smem);
    uint32_t BB = XB + XT_BYTES;

    int yw = w >> 1;              // out row within slab (0..7)
    int xh = w & 1;               // x half (0..1), 64 cols each

    uint32_t aoff = (uint32_t)(lane & 15) * (XT_XS * 2) +
                    (uint32_t)(lane >> 4) * 16u;
    uint32_t boff = (uint32_t)((((lane >> 4) & 1) * 8) + (lane & 7)) * SB_ROWB +
                    (uint32_t)((lane >> 3) & 1) * 16u;

    float d[4][4][4];
#pragma unroll
    for (int i = 0; i < 4; i++)
#pragma unroll
        for (int j = 0; j < 4; j++)
#pragma unroll
            for (int c = 0; c < 4; c++) d[i][j][c] = 0.0f;

    uint32_t awarp = XB + aoff + (uint32_t)yw * (XT_YS * 2) +
                     (uint32_t)xh * (64 * XT_XS * 2);
    uint32_t bwarp = BB + boff;

#pragma unroll 3
    for (int q = 0; q < 9; q++) {
        int ky = q / 3, kx = q - ky * 3;
        uint32_t aq = awarp + (uint32_t)ky * (XT_YS * 2) +
                      (uint32_t)kx * (XT_XS * 2);
        uint32_t bq = bwarp + (uint32_t)q * 64u;
#pragma unroll
        for (int h = 0; h < 2; h++) {
            uint32_t A[4][4], B0[4], B1[4];
#pragma unroll
            for (int i = 0; i < 4; i++)
                ldsm_x4(A[i], aq + h * 32u + (uint32_t)i * (16 * XT_XS * 2));
            ldsm_x4(B0, bq + h * 32u);
            ldsm_x4(B1, bq + h * 32u + 16u * SB_ROWB);
#pragma unroll
            for (int i = 0; i < 4; i++) {
                mma_f16(d[i][0], A[i], B0[0], B0[1]);
                mma_f16(d[i][1], A[i], B0[2], B0[3]);
                mma_f16(d[i][2], A[i], B1[0], B1[1]);
                mma_f16(d[i][3], A[i], B1[2], B1[3]);
            }
        }
    }

    int g  = lane >> 2;
    int tg = lane & 3;
    int yo = y0 + yw;
#pragma unroll
    for (int i = 0; i < 4; i++) {
        int xo = xh * 64 + i * 16 + g;
#pragma unroll
        for (int j = 0; j < 4; j++) {
            int co = j * 8 + tg * 2;
            float* p0 = out + (((size_t)(b * 32 + co)) * HWD + yo) * HWD + xo;
            p0[0]             = d[i][j][0];
            p0[HWD * HWD]     = d[i][j][1];
            p0[8]             = d[i][j][2];
            p0[HWD * HWD + 8] = d[i][j][3];
        }
    }
}

// ---------------------------------------------------------------------------
extern "C" void kernel_launch(void* const* d_in, const int* in_sizes, int n_in,
                              void* d_out, int out_size) {
    const float* x    = (const float*)d_in[0];
    const float* cond = (const float*)d_in[1];
    const float* W1   = (const float*)d_in[2];
    const float* b1   = (const float*)d_in[3];
    const float* W2   = (const float*)d_in[4];
    const float* b2   = (const float*)d_in[5];
    float* out = (float*)d_out;

    cudaFuncSetAttribute(conv_kernel,
                         cudaFuncAttributeMaxDynamicSharedMemorySize, CONV_SMEM);

    xprep_kernel<<<dim3(HWD, NB), 512>>>(x);
    mlp1_kernel<<<(HIDD * NB) / 256, 256>>>(cond, W1, b1);
    gemm2_kernel<<<NPARAM / GP, 128>>>(W2, b2);
    conv_kernel<<<dim3(16, NB), 512, CONV_SMEM>>>(out);
}

// round 13
// speedup vs baseline: 1.0634x; 1.0634x over previous
#include <cuda_runtime.h>
#include <cuda_fp16.h>
#include <cstdint>

#define NB   32
#define HWD  128
#define CONDD 256
#define HIDD 4608
#define NPARAM 9216

// Scratch (device globals: allocation-free rule)
__device__ __align__(16) __half g_hh[NB * HIDD];
#define WB_ROW   296
#define WB_ELEMS (32 * WB_ROW)              // 9472 per sample
__device__ __align__(16) __half g_wb[NB * WB_ELEMS];
// x fp16, layout [b][c4 0..3][y][x][cin8]  (32 MB)
__device__ __align__(16) __half g_xh[(size_t)NB * 4 * HWD * HWD * 8];

__device__ __forceinline__ uint32_t smem_to_u32(const void* p) {
    uint32_t a;
    asm("{ .reg .u64 t; cvta.to.shared.u64 t, %1; cvt.u32.u64 %0, t; }"
        : "=r"(a) : "l"(p));
    return a;
}

// ---------------------------------------------------------------------------
// warp-mma helpers
// ---------------------------------------------------------------------------
__device__ __forceinline__ void ldsm_x4(uint32_t r[4], uint32_t addr) {
    asm volatile("ldmatrix.sync.aligned.m8n8.x4.shared.b16 {%0,%1,%2,%3}, [%4];"
        : "=r"(r[0]), "=r"(r[1]), "=r"(r[2]), "=r"(r[3]) : "r"(addr));
}
__device__ __forceinline__ void mma_f16(float d[4], const uint32_t a[4],
                                        uint32_t b0, uint32_t b1) {
    asm volatile(
        "mma.sync.aligned.m16n8k16.row.col.f32.f16.f16.f32 "
        "{%0,%1,%2,%3}, {%4,%5,%6,%7}, {%8,%9}, {%0,%1,%2,%3};"
        : "+f"(d[0]), "+f"(d[1]), "+f"(d[2]), "+f"(d[3])
        : "r"(a[0]), "r"(a[1]), "r"(a[2]), "r"(a[3]), "r"(b0), "r"(b1));
}

// ---------------------------------------------------------------------------
// Kernel 0: x fp32 [b][cin][y][x] -> g_xh fp16 [b][c4][y][x][cin8]
// ---------------------------------------------------------------------------
__global__ void xprep_kernel(const float* __restrict__ x) {
    int b = blockIdx.y, y = blockIdx.x, t = threadIdx.x;   // 512 threads
    int c4 = t >> 7;
    int xx = t & 127;
    float v[8];
#pragma unroll
    for (int i = 0; i < 8; i++)
        v[i] = x[(((size_t)b * 32 + c4 * 8 + i) * HWD + y) * HWD + xx];
    __half2 h[4];
#pragma unroll
    for (int i = 0; i < 4; i++)
        h[i] = __floats2half2_rn(v[2 * i], v[2 * i + 1]);
    uint4 o = make_uint4(*(uint32_t*)&h[0], *(uint32_t*)&h[1],
                         *(uint32_t*)&h[2], *(uint32_t*)&h[3]);
    *(uint4*)(g_xh + ((((size_t)b * 4 + c4) * HWD + y) * HWD + xx) * 8) = o;
}

// ---------------------------------------------------------------------------
// Kernel 1: h = relu(cond @ W1^T + b1) -> g_hh fp16 [b][hid]
// ---------------------------------------------------------------------------
__global__ void mlp1_kernel(const float* __restrict__ cond,
                            const float* __restrict__ W1,
                            const float* __restrict__ b1) {
    int idx = blockIdx.x * blockDim.x + threadIdx.x;
    int hid = idx >> 5;
    int b   = idx & 31;
    const float4* c4 = (const float4*)(cond + b * CONDD);
    const float4* w4 = (const float4*)(W1 + (size_t)hid * CONDD);
    float acc = b1[hid];
#pragma unroll 8
    for (int i = 0; i < CONDD / 4; i++) {
        float4 cv = c4[i]; float4 wv = w4[i];
        acc += cv.x * wv.x + cv.y * wv.y + cv.z * wv.z + cv.w * wv.w;
    }
    g_hh[b * HIDD + hid] = __float2half_rn(fmaxf(acc, 0.0f));
}

// ---------------------------------------------------------------------------
// Kernel 2: tensor-core gemm2, double-buffered smem pipeline (kept from R12).
// CTA = 32 p-rows, 128 threads (4 warps = mh x nw), grid 288.
// ---------------------------------------------------------------------------
#define GP 32
#define GK 128
#define TST 272
#define SB_OFF 0                 // B tile: 32 rows
#define SA_OFF (32 * TST)        // A tile: 32 rows
#define G2_BUF (64 * TST)        // 17408 B per buffer
#define G2_SMEM (2 * G2_BUF)     // 34816 B

__global__ void __launch_bounds__(128, 2)
gemm2_kernel(const float* __restrict__ W2, const float* __restrict__ b2) {
    __shared__ __align__(16) unsigned char sm[G2_SMEM];

    int t = threadIdx.x, lane = t & 31, w = t >> 5;
    int pbase = blockIdx.x * GP;
    const int NCH = HIDD / GK;       // 36 chunks

    int brow = t >> 2;
    int bf4  = t & 3;
    const float4* W24 = (const float4*)(W2 + (size_t)(pbase + brow) * HIDD);
    int arow[4], ac[4];
#pragma unroll
    for (int i = 0; i < 4; i++) {
        int j = t + 128 * i; arow[i] = j >> 4; ac[i] = j & 15;
    }

    uint32_t SMB = smem_to_u32(sm);

    float4 rw[8]; uint4 rh[4];
    auto load_chunk = [&](int kc) {
        int ko = kc * 32;
#pragma unroll
        for (int i = 0; i < 8; i++) rw[i] = W24[ko + bf4 + 4 * i];
        int kh = kc * GK;
#pragma unroll
        for (int i = 0; i < 4; i++)
            rh[i] = *(const uint4*)(g_hh + (size_t)arow[i] * HIDD + kh + ac[i] * 8);
    };
    auto store_tiles = [&](uint32_t bofs) {
#pragma unroll
        for (int i = 0; i < 8; i++) {
            __half2 h0 = __floats2half2_rn(rw[i].x, rw[i].y);
            __half2 h1 = __floats2half2_rn(rw[i].z, rw[i].w);
            uint32_t u0 = *(uint32_t*)&h0, u1 = *(uint32_t*)&h1;
            uint32_t addr = SMB + bofs + SB_OFF + (uint32_t)brow * TST +
                            (uint32_t)(bf4 + 4 * i) * 8u;
            asm volatile("st.shared.v2.b32 [%0], {%1, %2};"
                         :: "r"(addr), "r"(u0), "r"(u1) : "memory");
        }
#pragma unroll
        for (int i = 0; i < 4; i++) {
            uint32_t a0 = SMB + bofs + SA_OFF + (uint32_t)arow[i] * TST + ac[i] * 16u;
            asm volatile("st.shared.v4.b32 [%0], {%1, %2, %3, %4};"
                :: "r"(a0), "r"(rh[i].x), "r"(rh[i].y), "r"(rh[i].z), "r"(rh[i].w) : "memory");
        }
    };

    int mh = w & 1;
    int nw = w >> 1;
    uint32_t Abase = SA_OFF +
        (uint32_t)(mh * 16 + (lane & 15)) * TST + (uint32_t)(lane >> 4) * 16u;
    uint32_t Bbase = SB_OFF +
        (uint32_t)(nw * 16 + (((lane >> 4) & 1) * 8) + (lane & 7)) * TST +
        (uint32_t)((lane >> 3) & 1) * 16u;

    float d0[4] = {0, 0, 0, 0}, d1[4] = {0, 0, 0, 0};

    load_chunk(0);
    store_tiles(0);
    load_chunk(1);
    __syncthreads();

    for (int kc = 0; kc < NCH; kc++) {
        uint32_t cur = (uint32_t)(kc & 1) * G2_BUF;
        if (kc + 1 < NCH) {
            store_tiles(G2_BUF - cur);
            if (kc + 2 < NCH) load_chunk(kc + 2);
        }
        __syncthreads();
#pragma unroll
        for (int ks = 0; ks < 8; ks++) {
            uint32_t A[4], B[4];
            ldsm_x4(A, SMB + cur + Abase + (uint32_t)ks * 32u);
            ldsm_x4(B, SMB + cur + Bbase + (uint32_t)ks * 32u);
            mma_f16(d0, A, B[0], B[1]);
            mma_f16(d1, A, B[2], B[3]);
        }
        __syncthreads();
    }

    int g  = lane >> 2;
    int tg = lane & 3;
#pragma unroll
    for (int j = 0; j < 2; j++) {
        const float* dj = (j == 0) ? d0 : d1;
#pragma unroll
        for (int c = 0; c < 2; c++) {
            int p = pbase + nw * 16 + j * 8 + tg * 2 + c;
            float bias = b2[p];
            int co = p / 288;
            int r  = p - co * 288;
            int cin = r / 9;
            int rr  = r - cin * 9;
            int k   = rr * 32 + cin;
            int b0 = mh * 16 + g;
            g_wb[(size_t)b0 * WB_ELEMS + co * WB_ROW + k] =
                __float2half_rn(dj[c] + bias);
            g_wb[(size_t)(b0 + 8) * WB_ELEMS + co * WB_ROW + k] =
                __float2half_rn(dj[2 + c] + bias);
        }
    }
}

// ---------------------------------------------------------------------------
// Kernel 3: warp-mma conv, fp16 — exact R11 version (measured 49.2 us).
// CTA = (b, 16 out rows, 64 out cols), 1024 threads = 32 warps:
// warp = (y 0..15, x-half 0..1), 2 mtiles x 4 ntiles, 4 ldsm -> 8 mma.
// ---------------------------------------------------------------------------
#define XT_XS 40
#define XT_YS (66 * XT_XS)
#define XT_ROWS 18
#define XT_ELEMS (XT_ROWS * XT_YS)
#define XT_BYTES (XT_ELEMS * 2)  // 95040 B
#define SB_ROWB (WB_ROW * 2)     // 592 B per co row
#define SB_BYTES (32 * SB_ROWB)  // 18944 B
#define CONV_SMEM (XT_BYTES + SB_BYTES)   // 113984 B

__global__ void __launch_bounds__(1024, 1)
conv_kernel(float* __restrict__ out) {
    extern __shared__ unsigned char smem[];
    uint4* s_b4 = (uint4*)(smem + XT_BYTES);

    int t = threadIdx.x, lane = t & 31, w = t >> 5;
    int b   = blockIdx.z;
    int y0  = blockIdx.y * 16;
    int x0g = blockIdx.x * 64;

    {
        const uint4* src = (const uint4*)(g_wb + (size_t)b * WB_ELEMS);
        for (int i = t; i < SB_BYTES / 16; i += 1024) s_b4[i] = src[i];
    }
    {
        const __half* xsrc = g_xh + (size_t)b * (4 * HWD * HWD * 8);
        for (int idx = t; idx < XT_ROWS * 66 * 4; idx += 1024) {
            int row = idx >> 2, c4 = idx & 3;
            int y  = row / 66, xx = row - y * 66;
            int gy = y0 - 1 + y, gx = x0g - 1 + xx;
            uint4 v = make_uint4(0, 0, 0, 0);
            if (gy >= 0 && gy < HWD && gx >= 0 && gx < HWD)
                v = *(const uint4*)(xsrc + (((size_t)c4 * HWD + gy) * HWD + gx) * 8);
            *(uint4*)(smem + (size_t)(y * XT_YS + xx * XT_XS) * 2 + c4 * 16) = v;
        }
    }
    __syncthreads();

    uint32_t XB = smem_to_u32(smem);
    uint32_t BB = XB + XT_BYTES;

    int yw = w >> 1;
    int xh = w & 1;

    uint32_t aoff = (uint32_t)(lane & 15) * (XT_XS * 2) +
                    (uint32_t)(lane >> 4) * 16u;
    uint32_t boff = (uint32_t)((((lane >> 4) & 1) * 8) + (lane & 7)) * SB_ROWB +
                    (uint32_t)((lane >> 3) & 1) * 16u;

    float d[2][4][4];
#pragma unroll
    for (int i = 0; i < 2; i++)
#pragma unroll
        for (int j = 0; j < 4; j++)
#pragma unroll
            for (int c = 0; c < 4; c++) d[i][j][c] = 0.0f;

    uint32_t awarp = XB + aoff + (uint32_t)yw * (XT_YS * 2) +
                     (uint32_t)xh * (32 * XT_XS * 2);
    uint32_t bwarp = BB + boff;

#pragma unroll 3
    for (int q = 0; q < 9; q++) {
        int ky = q / 3, kx = q - ky * 3;
        uint32_t aq = awarp + (uint32_t)ky * (XT_YS * 2) +
                      (uint32_t)kx * (XT_XS * 2);
        uint32_t bq = bwarp + (uint32_t)q * 64u;
#pragma unroll
        for (int h = 0; h < 2; h++) {
            uint32_t A0[4], A1[4], B0[4], B1[4];
            ldsm_x4(A0, aq + h * 32u);
            ldsm_x4(A1, aq + h * 32u + (16 * XT_XS * 2));
            ldsm_x4(B0, bq + h * 32u);
            ldsm_x4(B1, bq + h * 32u + 16u * SB_ROWB);
            mma_f16(d[0][0], A0, B0[0], B0[1]);
            mma_f16(d[0][1], A0, B0[2], B0[3]);
            mma_f16(d[0][2], A0, B1[0], B1[1]);
            mma_f16(d[0][3], A0, B1[2], B1[3]);
            mma_f16(d[1][0], A1, B0[0], B0[1]);
            mma_f16(d[1][1], A1, B0[2], B0[3]);
            mma_f16(d[1][2], A1, B1[0], B1[1]);
            mma_f16(d[1][3], A1, B1[2], B1[3]);
        }
    }

    int g  = lane >> 2;
    int tg = lane & 3;
    int yo = y0 + yw;
#pragma unroll
    for (int i = 0; i < 2; i++) {
        int xo = x0g + xh * 32 + i * 16 + g;
#pragma unroll
        for (int j = 0; j < 4; j++) {
            int co = j * 8 + tg * 2;
            float* p0 = out + (((size_t)(b * 32 + co)) * HWD + yo) * HWD + xo;
            p0[0]             = d[i][j][0];
            p0[HWD * HWD]     = d[i][j][1];
            p0[8]             = d[i][j][2];
            p0[HWD * HWD + 8] = d[i][j][3];
        }
    }
}

// ---------------------------------------------------------------------------
extern "C" void kernel_launch(void* const* d_in, const int* in_sizes, int n_in,
                              void* d_out, int out_size) {
    const float* x    = (const float*)d_in[0];
    const float* cond = (const float*)d_in[1];
    const float* W1   = (const float*)d_in[2];
    const float* b1   = (const float*)d_in[3];
    const float* W2   = (const float*)d_in[4];
    const float* b2   = (const float*)d_in[5];
    float* out = (float*)d_out;

    cudaFuncSetAttribute(conv_kernel,
                         cudaFuncAttributeMaxDynamicSharedMemorySize, CONV_SMEM);

    xprep_kernel<<<dim3(HWD, NB), 512>>>(x);
    mlp1_kernel<<<(HIDD * NB) / 256, 256>>>(cond, W1, b1);
    gemm2_kernel<<<NPARAM / GP, 128>>>(W2, b2);
    conv_kernel<<<dim3(2, 8, NB), 1024, CONV_SMEM>>>(out);
}

// round 14
// speedup vs baseline: 1.0729x; 1.0089x over previous
#include <cuda_runtime.h>
#include <cuda_fp16.h>
#include <cstdint>

#define NB   32
#define HWD  128
#define CONDD 256
#define HIDD 4608
#define NPARAM 9216

// Scratch (device globals: allocation-free rule)
__device__ __align__(16) __half g_hh[NB * HIDD];
#define WB_ROW   296
#define WB_ELEMS (32 * WB_ROW)              // 9472 per sample
__device__ __align__(16) __half g_wb[NB * WB_ELEMS];
// x fp16, layout [b][c4 0..3][y][x][cin8]  (32 MB)
__device__ __align__(16) __half g_xh[(size_t)NB * 4 * HWD * HWD * 8];

__device__ __forceinline__ uint32_t smem_to_u32(const void* p) {
    uint32_t a;
    asm("{ .reg .u64 t; cvta.to.shared.u64 t, %1; cvt.u32.u64 %0, t; }"
        : "=r"(a) : "l"(p));
    return a;
}

// ---------------------------------------------------------------------------
// warp-mma helpers
// ---------------------------------------------------------------------------
__device__ __forceinline__ void ldsm_x4(uint32_t r[4], uint32_t addr) {
    asm volatile("ldmatrix.sync.aligned.m8n8.x4.shared.b16 {%0,%1,%2,%3}, [%4];"
        : "=r"(r[0]), "=r"(r[1]), "=r"(r[2]), "=r"(r[3]) : "r"(addr));
}
__device__ __forceinline__ void mma_f16(float d[4], const uint32_t a[4],
                                        uint32_t b0, uint32_t b1) {
    asm volatile(
        "mma.sync.aligned.m16n8k16.row.col.f32.f16.f16.f32 "
        "{%0,%1,%2,%3}, {%4,%5,%6,%7}, {%8,%9}, {%0,%1,%2,%3};"
        : "+f"(d[0]), "+f"(d[1]), "+f"(d[2]), "+f"(d[3])
        : "r"(a[0]), "r"(a[1]), "r"(a[2]), "r"(a[3]), "r"(b0), "r"(b1));
}

// ---------------------------------------------------------------------------
// Kernel 1: h = relu(cond @ W1^T + b1) -> g_hh fp16 [b][hid]
// ---------------------------------------------------------------------------
__global__ void mlp1_kernel(const float* __restrict__ cond,
                            const float* __restrict__ W1,
                            const float* __restrict__ b1) {
    int idx = blockIdx.x * blockDim.x + threadIdx.x;
    int hid = idx >> 5;
    int b   = idx & 31;
    const float4* c4 = (const float4*)(cond + b * CONDD);
    const float4* w4 = (const float4*)(W1 + (size_t)hid * CONDD);
    float acc = b1[hid];
#pragma unroll 8
    for (int i = 0; i < CONDD / 4; i++) {
        float4 cv = c4[i]; float4 wv = w4[i];
        acc += cv.x * wv.x + cv.y * wv.y + cv.z * wv.z + cv.w * wv.w;
    }
    g_hh[b * HIDD + hid] = __float2half_rn(fmaxf(acc, 0.0f));
}

// ---------------------------------------------------------------------------
// Kernel 2 (FUSED): blocks [0,288) = tensor-core gemm2 (double-buffered,
// unchanged from R13); blocks [288, 288+4096) = xprep (x fp32 -> g_xh fp16).
// The two workloads are independent; xprep soaks DRAM bandwidth gemm2 leaves
// idle. Both outputs are consumed only by conv (next launch).
// ---------------------------------------------------------------------------
#define GP 32
#define GK 128
#define TST 272
#define SB_OFF 0                 // B tile: 32 rows
#define SA_OFF (32 * TST)        // A tile: 32 rows
#define G2_BUF (64 * TST)        // 17408 B per buffer
#define G2_SMEM (2 * G2_BUF)     // 34816 B
#define G2_BLOCKS (NPARAM / GP)  // 288

__global__ void __launch_bounds__(128, 2)
fused_gemm2_xprep_kernel(const float* __restrict__ W2,
                         const float* __restrict__ b2,
                         const float* __restrict__ x) {
    // ---------------- xprep path ----------------
    if (blockIdx.x >= G2_BLOCKS) {
        int bid = blockIdx.x - G2_BLOCKS;      // 0..4095
        int b = bid >> 7;                      // sample
        int y = bid & 127;                     // row
        int xx = threadIdx.x;                  // 0..127
#pragma unroll
        for (int c4 = 0; c4 < 4; c4++) {
            float v[8];
#pragma unroll
            for (int i = 0; i < 8; i++)
                v[i] = x[(((size_t)b * 32 + c4 * 8 + i) * HWD + y) * HWD + xx];
            __half2 h[4];
#pragma unroll
            for (int i = 0; i < 4; i++)
                h[i] = __floats2half2_rn(v[2 * i], v[2 * i + 1]);
            uint4 o = make_uint4(*(uint32_t*)&h[0], *(uint32_t*)&h[1],
                                 *(uint32_t*)&h[2], *(uint32_t*)&h[3]);
            *(uint4*)(g_xh + ((((size_t)b * 4 + c4) * HWD + y) * HWD + xx) * 8) = o;
        }
        return;
    }

    // ---------------- gemm2 path (identical to R13) ----------------
    __shared__ __align__(16) unsigned char sm[G2_SMEM];

    int t = threadIdx.x, lane = t & 31, w = t >> 5;
    int pbase = blockIdx.x * GP;
    const int NCH = HIDD / GK;       // 36 chunks

    int brow = t >> 2;
    int bf4  = t & 3;
    const float4* W24 = (const float4*)(W2 + (size_t)(pbase + brow) * HIDD);
    int arow[4], ac[4];
#pragma unroll
    for (int i = 0; i < 4; i++) {
        int j = t + 128 * i; arow[i] = j >> 4; ac[i] = j & 15;
    }

    uint32_t SMB = smem_to_u32(sm);

    float4 rw[8]; uint4 rh[4];
    auto load_chunk = [&](int kc) {
        int ko = kc * 32;
#pragma unroll
        for (int i = 0; i < 8; i++) rw[i] = W24[ko + bf4 + 4 * i];
        int kh = kc * GK;
#pragma unroll
        for (int i = 0; i < 4; i++)
            rh[i] = *(const uint4*)(g_hh + (size_t)arow[i] * HIDD + kh + ac[i] * 8);
    };
    auto store_tiles = [&](uint32_t bofs) {
#pragma unroll
        for (int i = 0; i < 8; i++) {
            __half2 h0 = __floats2half2_rn(rw[i].x, rw[i].y);
            __half2 h1 = __floats2half2_rn(rw[i].z, rw[i].w);
            uint32_t u0 = *(uint32_t*)&h0, u1 = *(uint32_t*)&h1;
            uint32_t addr = SMB + bofs + SB_OFF + (uint32_t)brow * TST +
                            (uint32_t)(bf4 + 4 * i) * 8u;
            asm volatile("st.shared.v2.b32 [%0], {%1, %2};"
                         :: "r"(addr), "r"(u0), "r"(u1) : "memory");
        }
#pragma unroll
        for (int i = 0; i < 4; i++) {
            uint32_t a0 = SMB + bofs + SA_OFF + (uint32_t)arow[i] * TST + ac[i] * 16u;
            asm volatile("st.shared.v4.b32 [%0], {%1, %2, %3, %4};"
                :: "r"(a0), "r"(rh[i].x), "r"(rh[i].y), "r"(rh[i].z), "r"(rh[i].w) : "memory");
        }
    };

    int mh = w & 1;
    int nw = w >> 1;
    uint32_t Abase = SA_OFF +
        (uint32_t)(mh * 16 + (lane & 15)) * TST + (uint32_t)(lane >> 4) * 16u;
    uint32_t Bbase = SB_OFF +
        (uint32_t)(nw * 16 + (((lane >> 4) & 1) * 8) + (lane & 7)) * TST +
        (uint32_t)((lane >> 3) & 1) * 16u;

    float d0[4] = {0, 0, 0, 0}, d1[4] = {0, 0, 0, 0};

    load_chunk(0);
    store_tiles(0);
    load_chunk(1);
    __syncthreads();

    for (int kc = 0; kc < NCH; kc++) {
        uint32_t cur = (uint32_t)(kc & 1) * G2_BUF;
        if (kc + 1 < NCH) {
            store_tiles(G2_BUF - cur);
            if (kc + 2 < NCH) load_chunk(kc + 2);
        }
        __syncthreads();
#pragma unroll
        for (int ks = 0; ks < 8; ks++) {
            uint32_t A[4], B[4];
            ldsm_x4(A, SMB + cur + Abase + (uint32_t)ks * 32u);
            ldsm_x4(B, SMB + cur + Bbase + (uint32_t)ks * 32u);
            mma_f16(d0, A, B[0], B[1]);
            mma_f16(d1, A, B[2], B[3]);
        }
        __syncthreads();
    }

    int g  = lane >> 2;
    int tg = lane & 3;
#pragma unroll
    for (int j = 0; j < 2; j++) {
        const float* dj = (j == 0) ? d0 : d1;
#pragma unroll
        for (int c = 0; c < 2; c++) {
            int p = pbase + nw * 16 + j * 8 + tg * 2 + c;
            float bias = b2[p];
            int co = p / 288;
            int r  = p - co * 288;
            int cin = r / 9;
            int rr  = r - cin * 9;
            int k   = rr * 32 + cin;
            int b0 = mh * 16 + g;
            g_wb[(size_t)b0 * WB_ELEMS + co * WB_ROW + k] =
                __float2half_rn(dj[c] + bias);
            g_wb[(size_t)(b0 + 8) * WB_ELEMS + co * WB_ROW + k] =
                __float2half_rn(dj[2 + c] + bias);
        }
    }
}

// ---------------------------------------------------------------------------
// Kernel 3: warp-mma conv, fp16 — exact R13 version (measured 49.6 us).
// ---------------------------------------------------------------------------
#define XT_XS 40
#define XT_YS (66 * XT_XS)
#define XT_ROWS 18
#define XT_ELEMS (XT_ROWS * XT_YS)
#define XT_BYTES (XT_ELEMS * 2)  // 95040 B
#define SB_ROWB (WB_ROW * 2)     // 592 B per co row
#define SB_BYTES (32 * SB_ROWB)  // 18944 B
#define CONV_SMEM (XT_BYTES + SB_BYTES)   // 113984 B

__global__ void __launch_bounds__(1024, 1)
conv_kernel(float* __restrict__ out) {
    extern __shared__ unsigned char smem[];
    uint4* s_b4 = (uint4*)(smem + XT_BYTES);

    int t = threadIdx.x, lane = t & 31, w = t >> 5;
    int b   = blockIdx.z;
    int y0  = blockIdx.y * 16;
    int x0g = blockIdx.x * 64;

    {
        const uint4* src = (const uint4*)(g_wb + (size_t)b * WB_ELEMS);
        for (int i = t; i < SB_BYTES / 16; i += 1024) s_b4[i] = src[i];
    }
    {
        const __half* xsrc = g_xh + (size_t)b * (4 * HWD * HWD * 8);
        for (int idx = t; idx < XT_ROWS * 66 * 4; idx += 1024) {
            int row = idx >> 2, c4 = idx & 3;
            int y  = row / 66, xx = row - y * 66;
            int gy = y0 - 1 + y, gx = x0g - 1 + xx;
            uint4 v = make_uint4(0, 0, 0, 0);
            if (gy >= 0 && gy < HWD && gx >= 0 && gx < HWD)
                v = *(const uint4*)(xsrc + (((size_t)c4 * HWD + gy) * HWD + gx) * 8);
            *(uint4*)(smem + (size_t)(y * XT_YS + xx * XT_XS) * 2 + c4 * 16) = v;
        }
    }
    __syncthreads();

    uint32_t XB = smem_to_u32(smem);
    uint32_t BB = XB + XT_BYTES;

    int yw = w >> 1;
    int xh = w & 1;

    uint32_t aoff = (uint32_t)(lane & 15) * (XT_XS * 2) +
                    (uint32_t)(lane >> 4) * 16u;
    uint32_t boff = (uint32_t)((((lane >> 4) & 1) * 8) + (lane & 7)) * SB_ROWB +
                    (uint32_t)((lane >> 3) & 1) * 16u;

    float d[2][4][4];
#pragma unroll
    for (int i = 0; i < 2; i++)
#pragma unroll
        for (int j = 0; j < 4; j++)
#pragma unroll
            for (int c = 0; c < 4; c++) d[i][j][c] = 0.0f;

    uint32_t awarp = XB + aoff + (uint32_t)yw * (XT_YS * 2) +
                     (uint32_t)xh * (32 * XT_XS * 2);
    uint32_t bwarp = BB + boff;

#pragma unroll 3
    for (int q = 0; q < 9; q++) {
        int ky = q / 3, kx = q - ky * 3;
        uint32_t aq = awarp + (uint32_t)ky * (XT_YS * 2) +
                      (uint32_t)kx * (XT_XS * 2);
        uint32_t bq = bwarp + (uint32_t)q * 64u;
#pragma unroll
        for (int h = 0; h < 2; h++) {
            uint32_t A0[4], A1[4], B0[4], B1[4];
            ldsm_x4(A0, aq + h * 32u);
            ldsm_x4(A1, aq + h * 32u + (16 * XT_XS * 2));
            ldsm_x4(B0, bq + h * 32u);
            ldsm_x4(B1, bq + h * 32u + 16u * SB_ROWB);
            mma_f16(d[0][0], A0, B0[0], B0[1]);
            mma_f16(d[0][1], A0, B0[2], B0[3]);
            mma_f16(d[0][2], A0, B1[0], B1[1]);
            mma_f16(d[0][3], A0, B1[2], B1[3]);
            mma_f16(d[1][0], A1, B0[0], B0[1]);
            mma_f16(d[1][1], A1, B0[2], B0[3]);
            mma_f16(d[1][2], A1, B1[0], B1[1]);
            mma_f16(d[1][3], A1, B1[2], B1[3]);
        }
    }

    int g  = lane >> 2;
    int tg = lane & 3;
    int yo = y0 + yw;
#pragma unroll
    for (int i = 0; i < 2; i++) {
        int xo = x0g + xh * 32 + i * 16 + g;
#pragma unroll
        for (int j = 0; j < 4; j++) {
            int co = j * 8 + tg * 2;
            float* p0 = out + (((size_t)(b * 32 + co)) * HWD + yo) * HWD + xo;
            p0[0]             = d[i][j][0];
            p0[HWD * HWD]     = d[i][j][1];
            p0[8]             = d[i][j][2];
            p0[HWD * HWD + 8] = d[i][j][3];
        }
    }
}

// ---------------------------------------------------------------------------
extern "C" void kernel_launch(void* const* d_in, const int* in_sizes, int n_in,
                              void* d_out, int out_size) {
    const float* x    = (const float*)d_in[0];
    const float* cond = (const float*)d_in[1];
    const float* W1   = (const float*)d_in[2];
    const float* b1   = (const float*)d_in[3];
    const float* W2   = (const float*)d_in[4];
    const float* b2   = (const float*)d_in[5];
    float* out = (float*)d_out;

    cudaFuncSetAttribute(conv_kernel,
                         cudaFuncAttributeMaxDynamicSharedMemorySize, CONV_SMEM);

    mlp1_kernel<<<(HIDD * NB) / 256, 256>>>(cond, W1, b1);
    fused_gemm2_xprep_kernel<<<G2_BLOCKS + NB * HWD, 128>>>(W2, b2, x);
    conv_kernel<<<dim3(2, 8, NB), 1024, CONV_SMEM>>>(out);
}

// round 15
// speedup vs baseline: 1.1299x; 1.0531x over previous
#include <cuda_runtime.h>
#include <cuda_fp16.h>
#include <cstdint>

#define NB   32
#define HWD  128
#define CONDD 256
#define HIDD 4608
#define NPARAM 9216

// Scratch (device globals: allocation-free rule)
__device__ __align__(16) __half g_hh[NB * HIDD];
#define WB_ROW   296
#define WB_ELEMS (32 * WB_ROW)              // 9472 per sample
__device__ __align__(16) __half g_wb[NB * WB_ELEMS];
// x fp16, layout [b][c4 0..3][y][x][cin8]  (32 MB)
__device__ __align__(16) __half g_xh[(size_t)NB * 4 * HWD * HWD * 8];

__device__ __forceinline__ uint32_t smem_to_u32(const void* p) {
    uint32_t a;
    asm("{ .reg .u64 t; cvta.to.shared.u64 t, %1; cvt.u32.u64 %0, t; }"
        : "=r"(a) : "l"(p));
    return a;
}

// ---------------------------------------------------------------------------
// warp-mma helpers
// ---------------------------------------------------------------------------
__device__ __forceinline__ void ldsm_x4(uint32_t r[4], uint32_t addr) {
    asm volatile("ldmatrix.sync.aligned.m8n8.x4.shared.b16 {%0,%1,%2,%3}, [%4];"
        : "=r"(r[0]), "=r"(r[1]), "=r"(r[2]), "=r"(r[3]) : "r"(addr));
}
__device__ __forceinline__ void mma_f16(float d[4], const uint32_t a[4],
                                        uint32_t b0, uint32_t b1) {
    asm volatile(
        "mma.sync.aligned.m16n8k16.row.col.f32.f16.f16.f32 "
        "{%0,%1,%2,%3}, {%4,%5,%6,%7}, {%8,%9}, {%0,%1,%2,%3};"
        : "+f"(d[0]), "+f"(d[1]), "+f"(d[2]), "+f"(d[3])
        : "r"(a[0]), "r"(a[1]), "r"(a[2]), "r"(a[3]), "r"(b0), "r"(b1));
}

// ---------------------------------------------------------------------------
// Kernel 1: h = relu(cond @ W1^T + b1) -> g_hh fp16 [b][hid]
// cond staged in smem TRANSPOSED (s_c[i][b]) so lane b reads bank b —
// conflict-free; W1 loads are warp-broadcast (one line per request).
// ---------------------------------------------------------------------------
__global__ void mlp1_kernel(const float* __restrict__ cond,
                            const float* __restrict__ W1,
                            const float* __restrict__ b1) {
    __shared__ float s_c[CONDD][32];       // 32 KB, bank(b) = b
    int t = threadIdx.x;

    // load cond[b][i] -> s_c[i][b]; lane = b so STS is conflict-free
    for (int j = t; j < 32 * CONDD; j += 256) {
        int b = j & 31;
        int i = j >> 5;
        s_c[i][b] = cond[b * CONDD + i];
    }
    __syncthreads();

    int idx = blockIdx.x * 256 + t;
    int hid = idx >> 5;                    // constant within warp
    int b   = idx & 31;                    // = lane
    const float4* w4 = (const float4*)(W1 + (size_t)hid * CONDD);
    float acc = b1[hid];
#pragma unroll 8
    for (int i = 0; i < CONDD / 4; i++) {
        float4 wv = w4[i];                 // broadcast
        acc += wv.x * s_c[4 * i + 0][b] + wv.y * s_c[4 * i + 1][b] +
               wv.z * s_c[4 * i + 2][b] + wv.w * s_c[4 * i + 3][b];
    }
    g_hh[b * HIDD + hid] = __float2half_rn(fmaxf(acc, 0.0f));
}

// ---------------------------------------------------------------------------
// Kernel 2 (FUSED): blocks [0,288) = tensor-core gemm2 (double-buffered);
// blocks [288, 288+4096) = xprep (x fp32 -> g_xh fp16). Unchanged from R14.
// ---------------------------------------------------------------------------
#define GP 32
#define GK 128
#define TST 272
#define SB_OFF 0                 // B tile: 32 rows
#define SA_OFF (32 * TST)        // A tile: 32 rows
#define G2_BUF (64 * TST)        // 17408 B per buffer
#define G2_SMEM (2 * G2_BUF)     // 34816 B
#define G2_BLOCKS (NPARAM / GP)  // 288

__global__ void __launch_bounds__(128, 2)
fused_gemm2_xprep_kernel(const float* __restrict__ W2,
                         const float* __restrict__ b2,
                         const float* __restrict__ x) {
    // ---------------- xprep path ----------------
    if (blockIdx.x >= G2_BLOCKS) {
        int bid = blockIdx.x - G2_BLOCKS;      // 0..4095
        int b = bid >> 7;                      // sample
        int y = bid & 127;                     // row
        int xx = threadIdx.x;                  // 0..127
#pragma unroll
        for (int c4 = 0; c4 < 4; c4++) {
            float v[8];
#pragma unroll
            for (int i = 0; i < 8; i++)
                v[i] = x[(((size_t)b * 32 + c4 * 8 + i) * HWD + y) * HWD + xx];
            __half2 h[4];
#pragma unroll
            for (int i = 0; i < 4; i++)
                h[i] = __floats2half2_rn(v[2 * i], v[2 * i + 1]);
            uint4 o = make_uint4(*(uint32_t*)&h[0], *(uint32_t*)&h[1],
                                 *(uint32_t*)&h[2], *(uint32_t*)&h[3]);
            *(uint4*)(g_xh + ((((size_t)b * 4 + c4) * HWD + y) * HWD + xx) * 8) = o;
        }
        return;
    }

    // ---------------- gemm2 path ----------------
    __shared__ __align__(16) unsigned char sm[G2_SMEM];

    int t = threadIdx.x, lane = t & 31, w = t >> 5;
    int pbase = blockIdx.x * GP;
    const int NCH = HIDD / GK;       // 36 chunks

    int brow = t >> 2;
    int bf4  = t & 3;
    const float4* W24 = (const float4*)(W2 + (size_t)(pbase + brow) * HIDD);
    int arow[4], ac[4];
#pragma unroll
    for (int i = 0; i < 4; i++) {
        int j = t + 128 * i; arow[i] = j >> 4; ac[i] = j & 15;
    }

    uint32_t SMB = smem_to_u32(sm);

    float4 rw[8]; uint4 rh[4];
    auto load_chunk = [&](int kc) {
        int ko = kc * 32;
#pragma unroll
        for (int i = 0; i < 8; i++) rw[i] = W24[ko + bf4 + 4 * i];
        int kh = kc * GK;
#pragma unroll
        for (int i = 0; i < 4; i++)
            rh[i] = *(const uint4*)(g_hh + (size_t)arow[i] * HIDD + kh + ac[i] * 8);
    };
    auto store_tiles = [&](uint32_t bofs) {
#pragma unroll
        for (int i = 0; i < 8; i++) {
            __half2 h0 = __floats2half2_rn(rw[i].x, rw[i].y);
            __half2 h1 = __floats2half2_rn(rw[i].z, rw[i].w);
            uint32_t u0 = *(uint32_t*)&h0, u1 = *(uint32_t*)&h1;
            uint32_t addr = SMB + bofs + SB_OFF + (uint32_t)brow * TST +
                            (uint32_t)(bf4 + 4 * i) * 8u;
            asm volatile("st.shared.v2.b32 [%0], {%1, %2};"
                         :: "r"(addr), "r"(u0), "r"(u1) : "memory");
        }
#pragma unroll
        for (int i = 0; i < 4; i++) {
            uint32_t a0 = SMB + bofs + SA_OFF + (uint32_t)arow[i] * TST + ac[i] * 16u;
            asm volatile("st.shared.v4.b32 [%0], {%1, %2, %3, %4};"
                :: "r"(a0), "r"(rh[i].x), "r"(rh[i].y), "r"(rh[i].z), "r"(rh[i].w) : "memory");
        }
    };

    int mh = w & 1;
    int nw = w >> 1;
    uint32_t Abase = SA_OFF +
        (uint32_t)(mh * 16 + (lane & 15)) * TST + (uint32_t)(lane >> 4) * 16u;
    uint32_t Bbase = SB_OFF +
        (uint32_t)(nw * 16 + (((lane >> 4) & 1) * 8) + (lane & 7)) * TST +
        (uint32_t)((lane >> 3) & 1) * 16u;

    float d0[4] = {0, 0, 0, 0}, d1[4] = {0, 0, 0, 0};

    load_chunk(0);
    store_tiles(0);
    load_chunk(1);
    __syncthreads();

    for (int kc = 0; kc < NCH; kc++) {
        uint32_t cur = (uint32_t)(kc & 1) * G2_BUF;
        if (kc + 1 < NCH) {
            store_tiles(G2_BUF - cur);
            if (kc + 2 < NCH) load_chunk(kc + 2);
        }
        __syncthreads();
#pragma unroll
        for (int ks = 0; ks < 8; ks++) {
            uint32_t A[4], B[4];
            ldsm_x4(A, SMB + cur + Abase + (uint32_t)ks * 32u);
            ldsm_x4(B, SMB + cur + Bbase + (uint32_t)ks * 32u);
            mma_f16(d0, A, B[0], B[1]);
            mma_f16(d1, A, B[2], B[3]);
        }
        __syncthreads();
    }

    int g  = lane >> 2;
    int tg = lane & 3;
#pragma unroll
    for (int j = 0; j < 2; j++) {
        const float* dj = (j == 0) ? d0 : d1;
#pragma unroll
        for (int c = 0; c < 2; c++) {
            int p = pbase + nw * 16 + j * 8 + tg * 2 + c;
            float bias = b2[p];
            int co = p / 288;
            int r  = p - co * 288;
            int cin = r / 9;
            int rr  = r - cin * 9;
            int k   = rr * 32 + cin;
            int b0 = mh * 16 + g;
            g_wb[(size_t)b0 * WB_ELEMS + co * WB_ROW + k] =
                __float2half_rn(dj[c] + bias);
            g_wb[(size_t)(b0 + 8) * WB_ELEMS + co * WB_ROW + k] =
                __float2half_rn(dj[2 + c] + bias);
        }
    }
}

// ---------------------------------------------------------------------------
// Kernel 3: warp-mma conv, fp16 — unchanged (measured 49.6 us).
// ---------------------------------------------------------------------------
#define XT_XS 40
#define XT_YS (66 * XT_XS)
#define XT_ROWS 18
#define XT_ELEMS (XT_ROWS * XT_YS)
#define XT_BYTES (XT_ELEMS * 2)  // 95040 B
#define SB_ROWB (WB_ROW * 2)     // 592 B per co row
#define SB_BYTES (32 * SB_ROWB)  // 18944 B
#define CONV_SMEM (XT_BYTES + SB_BYTES)   // 113984 B

__global__ void __launch_bounds__(1024, 1)
conv_kernel(float* __restrict__ out) {
    extern __shared__ unsigned char smem[];
    uint4* s_b4 = (uint4*)(smem + XT_BYTES);

    int t = threadIdx.x, lane = t & 31, w = t >> 5;
    int b   = blockIdx.z;
    int y0  = blockIdx.y * 16;
    int x0g = blockIdx.x * 64;

    {
        const uint4* src = (const uint4*)(g_wb + (size_t)b * WB_ELEMS);
        for (int i = t; i < SB_BYTES / 16; i += 1024) s_b4[i] = src[i];
    }
    {
        const __half* xsrc = g_xh + (size_t)b * (4 * HWD * HWD * 8);
        for (int idx = t; idx < XT_ROWS * 66 * 4; idx += 1024) {
            int row = idx >> 2, c4 = idx & 3;
            int y  = row / 66, xx = row - y * 66;
            int gy = y0 - 1 + y, gx = x0g - 1 + xx;
            uint4 v = make_uint4(0, 0, 0, 0);
            if (gy >= 0 && gy < HWD && gx >= 0 && gx < HWD)
                v = *(const uint4*)(xsrc + (((size_t)c4 * HWD + gy) * HWD + gx) * 8);
            *(uint4*)(smem + (size_t)(y * XT_YS + xx * XT_XS) * 2 + c4 * 16) = v;
        }
    }
    __syncthreads();

    uint32_t XB = smem_to_u32(smem);
    uint32_t BB = XB + XT_BYTES;

    int yw = w >> 1;
    int xh = w & 1;

    uint32_t aoff = (uint32_t)(lane & 15) * (XT_XS * 2) +
                    (uint32_t)(lane >> 4) * 16u;
    uint32_t boff = (uint32_t)((((lane >> 4) & 1) * 8) + (lane & 7)) * SB_ROWB +
                    (uint32_t)((lane >> 3) & 1) * 16u;

    float d[2][4][4];
#pragma unroll
    for (int i = 0; i < 2; i++)
#pragma unroll
        for (int j = 0; j < 4; j++)
#pragma unroll
            for (int c = 0; c < 4; c++) d[i][j][c] = 0.0f;

    uint32_t awarp = XB + aoff + (uint32_t)yw * (XT_YS * 2) +
                     (uint32_t)xh * (32 * XT_XS * 2);
    uint32_t bwarp = BB + boff;

#pragma unroll 3
    for (int q = 0; q < 9; q++) {
        int ky = q / 3, kx = q - ky * 3;
        uint32_t aq = awarp + (uint32_t)ky * (XT_YS * 2) +
                      (uint32_t)kx * (XT_XS * 2);
        uint32_t bq = bwarp + (uint32_t)q * 64u;
#pragma unroll
        for (int h = 0; h < 2; h++) {
            uint32_t A0[4], A1[4], B0[4], B1[4];
            ldsm_x4(A0, aq + h * 32u);
            ldsm_x4(A1, aq + h * 32u + (16 * XT_XS * 2));
            ldsm_x4(B0, bq + h * 32u);
            ldsm_x4(B1, bq + h * 32u + 16u * SB_ROWB);
            mma_f16(d[0][0], A0, B0[0], B0[1]);
            mma_f16(d[0][1], A0, B0[2], B0[3]);
            mma_f16(d[0][2], A0, B1[0], B1[1]);
            mma_f16(d[0][3], A0, B1[2], B1[3]);
            mma_f16(d[1][0], A1, B0[0], B0[1]);
            mma_f16(d[1][1], A1, B0[2], B0[3]);
            mma_f16(d[1][2], A1, B1[0], B1[1]);
            mma_f16(d[1][3], A1, B1[2], B1[3]);
        }
    }

    int g  = lane >> 2;
    int tg = lane & 3;
    int yo = y0 + yw;
#pragma unroll
    for (int i = 0; i < 2; i++) {
        int xo = x0g + xh * 32 + i * 16 + g;
#pragma unroll
        for (int j = 0; j < 4; j++) {
            int co = j * 8 + tg * 2;
            float* p0 = out + (((size_t)(b * 32 + co)) * HWD + yo) * HWD + xo;
            p0[0]             = d[i][j][0];
            p0[HWD * HWD]     = d[i][j][1];
            p0[8]             = d[i][j][2];
            p0[HWD * HWD + 8] = d[i][j][3];
        }
    }
}

// ---------------------------------------------------------------------------
extern "C" void kernel_launch(void* const* d_in, const int* in_sizes, int n_in,
                              void* d_out, int out_size) {
    const float* x    = (const float*)d_in[0];
    const float* cond = (const float*)d_in[1];
    const float* W1   = (const float*)d_in[2];
    const float* b1   = (const float*)d_in[3];
    const float* W2   = (const float*)d_in[4];
    const float* b2   = (const float*)d_in[5];
    float* out = (float*)d_out;

    cudaFuncSetAttribute(conv_kernel,
                         cudaFuncAttributeMaxDynamicSharedMemorySize, CONV_SMEM);

    mlp1_kernel<<<(HIDD * NB) / 256, 256>>>(cond, W1, b1);
    fused_gemm2_xprep_kernel<<<G2_BLOCKS + NB * HWD, 128>>>(W2, b2, x);
    conv_kernel<<<dim3(2, 8, NB), 1024, CONV_SMEM>>>(out);
}

// round 16
// speedup vs baseline: 1.2788x; 1.1318x over previous
#include <cuda_runtime.h>
#include <cuda_fp16.h>
#include <cstdint>

#define NB   32
#define HWD  128
#define CONDD 256
#define HIDD 4608
#define NPARAM 9216

// Scratch (device globals: allocation-free rule)
__device__ __align__(16) __half g_hh[NB * HIDD];
#define WB_ROW   296
#define WB_ELEMS (32 * WB_ROW)              // 9472 per sample
__device__ __align__(16) __half g_wb[NB * WB_ELEMS];
// x fp16, layout [b][c4 0..3][y][x][cin8]  (32 MB)
__device__ __align__(16) __half g_xh[(size_t)NB * 4 * HWD * HWD * 8];

__device__ __forceinline__ uint32_t smem_to_u32(const void* p) {
    uint32_t a;
    asm("{ .reg .u64 t; cvta.to.shared.u64 t, %1; cvt.u32.u64 %0, t; }"
        : "=r"(a) : "l"(p));
    return a;
}

// ---------------------------------------------------------------------------
// warp-mma helpers
// ---------------------------------------------------------------------------
__device__ __forceinline__ void ldsm_x4(uint32_t r[4], uint32_t addr) {
    asm volatile("ldmatrix.sync.aligned.m8n8.x4.shared.b16 {%0,%1,%2,%3}, [%4];"
        : "=r"(r[0]), "=r"(r[1]), "=r"(r[2]), "=r"(r[3]) : "r"(addr));
}
__device__ __forceinline__ void mma_f16(float d[4], const uint32_t a[4],
                                        uint32_t b0, uint32_t b1) {
    asm volatile(
        "mma.sync.aligned.m16n8k16.row.col.f32.f16.f16.f32 "
        "{%0,%1,%2,%3}, {%4,%5,%6,%7}, {%8,%9}, {%0,%1,%2,%3};"
        : "+f"(d[0]), "+f"(d[1]), "+f"(d[2]), "+f"(d[3])
        : "r"(a[0]), "r"(a[1]), "r"(a[2]), "r"(a[3]), "r"(b0), "r"(b1));
}

// ---------------------------------------------------------------------------
// Kernel 1: h = relu(cond @ W1^T + b1) -> g_hh fp16 [b][hid]
// Coalesced cond staging (lane walks i), bank-safe padded smem [256][33],
// 8 independent accumulators to break the FMA RAW chain.
// ---------------------------------------------------------------------------
__global__ void mlp1_kernel(const float* __restrict__ cond,
                            const float* __restrict__ W1,
                            const float* __restrict__ b1) {
    __shared__ float s_c[CONDD][33];
    int t = threadIdx.x;

    // coalesced: warp reads consecutive i of one cond row; STS column is
    // bank-free thanks to the 33-stride padding.
    for (int j = t; j < 32 * CONDD; j += 256) {
        int b = j >> 8;            // 0..31
        int i = j & 255;
        s_c[i][b] = cond[b * CONDD + i];
    }
    __syncthreads();

    int idx = blockIdx.x * 256 + t;
    int hid = idx >> 5;            // constant within warp
    int b   = idx & 31;            // = lane
    const float4* w4 = (const float4*)(W1 + (size_t)hid * CONDD);

    float a0 = 0.f, a1 = 0.f, a2 = 0.f, a3 = 0.f;
    float a4 = 0.f, a5 = 0.f, a6 = 0.f, a7 = 0.f;
#pragma unroll 8
    for (int i = 0; i < CONDD / 4; i += 2) {
        float4 w0 = w4[i];         // broadcast
        float4 w1 = w4[i + 1];
        a0 += w0.x * s_c[4 * i + 0][b];
        a1 += w0.y * s_c[4 * i + 1][b];
        a2 += w0.z * s_c[4 * i + 2][b];
        a3 += w0.w * s_c[4 * i + 3][b];
        a4 += w1.x * s_c[4 * i + 4][b];
        a5 += w1.y * s_c[4 * i + 5][b];
        a6 += w1.z * s_c[4 * i + 6][b];
        a7 += w1.w * s_c[4 * i + 7][b];
    }
    float acc = b1[hid] + (((a0 + a1) + (a2 + a3)) + ((a4 + a5) + (a6 + a7)));
    g_hh[b * HIDD + hid] = __float2half_rn(fmaxf(acc, 0.0f));
}

// ---------------------------------------------------------------------------
// Kernel 2 (FUSED): blocks [0,288) = tensor-core gemm2 (double-buffered);
// blocks [288, 288+4096) = xprep (x fp32 -> g_xh fp16). Unchanged.
// ---------------------------------------------------------------------------
#define GP 32
#define GK 128
#define TST 272
#define SB_OFF 0                 // B tile: 32 rows
#define SA_OFF (32 * TST)        // A tile: 32 rows
#define G2_BUF (64 * TST)        // 17408 B per buffer
#define G2_SMEM (2 * G2_BUF)     // 34816 B
#define G2_BLOCKS (NPARAM / GP)  // 288

__global__ void __launch_bounds__(128, 2)
fused_gemm2_xprep_kernel(const float* __restrict__ W2,
                         const float* __restrict__ b2,
                         const float* __restrict__ x) {
    // ---------------- xprep path ----------------
    if (blockIdx.x >= G2_BLOCKS) {
        int bid = blockIdx.x - G2_BLOCKS;      // 0..4095
        int b = bid >> 7;                      // sample
        int y = bid & 127;                     // row
        int xx = threadIdx.x;                  // 0..127
#pragma unroll
        for (int c4 = 0; c4 < 4; c4++) {
            float v[8];
#pragma unroll
            for (int i = 0; i < 8; i++)
                v[i] = x[(((size_t)b * 32 + c4 * 8 + i) * HWD + y) * HWD + xx];
            __half2 h[4];
#pragma unroll
            for (int i = 0; i < 4; i++)
                h[i] = __floats2half2_rn(v[2 * i], v[2 * i + 1]);
            uint4 o = make_uint4(*(uint32_t*)&h[0], *(uint32_t*)&h[1],
                                 *(uint32_t*)&h[2], *(uint32_t*)&h[3]);
            *(uint4*)(g_xh + ((((size_t)b * 4 + c4) * HWD + y) * HWD + xx) * 8) = o;
        }
        return;
    }

    // ---------------- gemm2 path ----------------
    __shared__ __align__(16) unsigned char sm[G2_SMEM];

    int t = threadIdx.x, lane = t & 31, w = t >> 5;
    int pbase = blockIdx.x * GP;
    const int NCH = HIDD / GK;       // 36 chunks

    int brow = t >> 2;
    int bf4  = t & 3;
    const float4* W24 = (const float4*)(W2 + (size_t)(pbase + brow) * HIDD);
    int arow[4], ac[4];
#pragma unroll
    for (int i = 0; i < 4; i++) {
        int j = t + 128 * i; arow[i] = j >> 4; ac[i] = j & 15;
    }

    uint32_t SMB = smem_to_u32(sm);

    float4 rw[8]; uint4 rh[4];
    auto load_chunk = [&](int kc) {
        int ko = kc * 32;
#pragma unroll
        for (int i = 0; i < 8; i++) rw[i] = W24[ko + bf4 + 4 * i];
        int kh = kc * GK;
#pragma unroll
        for (int i = 0; i < 4; i++)
            rh[i] = *(const uint4*)(g_hh + (size_t)arow[i] * HIDD + kh + ac[i] * 8);
    };
    auto store_tiles = [&](uint32_t bofs) {
#pragma unroll
        for (int i = 0; i < 8; i++) {
            __half2 h0 = __floats2half2_rn(rw[i].x, rw[i].y);
            __half2 h1 = __floats2half2_rn(rw[i].z, rw[i].w);
            uint32_t u0 = *(uint32_t*)&h0, u1 = *(uint32_t*)&h1;
            uint32_t addr = SMB + bofs + SB_OFF + (uint32_t)brow * TST +
                            (uint32_t)(bf4 + 4 * i) * 8u;
            asm volatile("st.shared.v2.b32 [%0], {%1, %2};"
                         :: "r"(addr), "r"(u0), "r"(u1) : "memory");
        }
#pragma unroll
        for (int i = 0; i < 4; i++) {
            uint32_t a0 = SMB + bofs + SA_OFF + (uint32_t)arow[i] * TST + ac[i] * 16u;
            asm volatile("st.shared.v4.b32 [%0], {%1, %2, %3, %4};"
                :: "r"(a0), "r"(rh[i].x), "r"(rh[i].y), "r"(rh[i].z), "r"(rh[i].w) : "memory");
        }
    };

    int mh = w & 1;
    int nw = w >> 1;
    uint32_t Abase = SA_OFF +
        (uint32_t)(mh * 16 + (lane & 15)) * TST + (uint32_t)(lane >> 4) * 16u;
    uint32_t Bbase = SB_OFF +
        (uint32_t)(nw * 16 + (((lane >> 4) & 1) * 8) + (lane & 7)) * TST +
        (uint32_t)((lane >> 3) & 1) * 16u;

    float d0[4] = {0, 0, 0, 0}, d1[4] = {0, 0, 0, 0};

    load_chunk(0);
    store_tiles(0);
    load_chunk(1);
    __syncthreads();

    for (int kc = 0; kc < NCH; kc++) {
        uint32_t cur = (uint32_t)(kc & 1) * G2_BUF;
        if (kc + 1 < NCH) {
            store_tiles(G2_BUF - cur);
            if (kc + 2 < NCH) load_chunk(kc + 2);
        }
        __syncthreads();
#pragma unroll
        for (int ks = 0; ks < 8; ks++) {
            uint32_t A[4], B[4];
            ldsm_x4(A, SMB + cur + Abase + (uint32_t)ks * 32u);
            ldsm_x4(B, SMB + cur + Bbase + (uint32_t)ks * 32u);
            mma_f16(d0, A, B[0], B[1]);
            mma_f16(d1, A, B[2], B[3]);
        }
        __syncthreads();
    }

    int g  = lane >> 2;
    int tg = lane & 3;
#pragma unroll
    for (int j = 0; j < 2; j++) {
        const float* dj = (j == 0) ? d0 : d1;
#pragma unroll
        for (int c = 0; c < 2; c++) {
            int p = pbase + nw * 16 + j * 8 + tg * 2 + c;
            float bias = b2[p];
            int co = p / 288;
            int r  = p - co * 288;
            int cin = r / 9;
            int rr  = r - cin * 9;
            int k   = rr * 32 + cin;
            int b0 = mh * 16 + g;
            g_wb[(size_t)b0 * WB_ELEMS + co * WB_ROW + k] =
                __float2half_rn(dj[c] + bias);
            g_wb[(size_t)(b0 + 8) * WB_ELEMS + co * WB_ROW + k] =
                __float2half_rn(dj[2 + c] + bias);
        }
    }
}

// ---------------------------------------------------------------------------
// Kernel 3: warp-mma conv, fp16 — unchanged (measured 49.6 us).
// ---------------------------------------------------------------------------
#define XT_XS 40
#define XT_YS (66 * XT_XS)
#define XT_ROWS 18
#define XT_ELEMS (XT_ROWS * XT_YS)
#define XT_BYTES (XT_ELEMS * 2)  // 95040 B
#define SB_ROWB (WB_ROW * 2)     // 592 B per co row
#define SB_BYTES (32 * SB_ROWB)  // 18944 B
#define CONV_SMEM (XT_BYTES + SB_BYTES)   // 113984 B

__global__ void __launch_bounds__(1024, 1)
conv_kernel(float* __restrict__ out) {
    extern __shared__ unsigned char smem[];
    uint4* s_b4 = (uint4*)(smem + XT_BYTES);

    int t = threadIdx.x, lane = t & 31, w = t >> 5;
    int b   = blockIdx.z;
    int y0  = blockIdx.y * 16;
    int x0g = blockIdx.x * 64;

    {
        const uint4* src = (const uint4*)(g_wb + (size_t)b * WB_ELEMS);
        for (int i = t; i < SB_BYTES / 16; i += 1024) s_b4[i] = src[i];
    }
    {
        const __half* xsrc = g_xh + (size_t)b * (4 * HWD * HWD * 8);
        for (int idx = t; idx < XT_ROWS * 66 * 4; idx += 1024) {
            int row = idx >> 2, c4 = idx & 3;
            int y  = row / 66, xx = row - y * 66;
            int gy = y0 - 1 + y, gx = x0g - 1 + xx;
            uint4 v = make_uint4(0, 0, 0, 0);
            if (gy >= 0 && gy < HWD && gx >= 0 && gx < HWD)
                v = *(const uint4*)(xsrc + (((size_t)c4 * HWD + gy) * HWD + gx) * 8);
            *(uint4*)(smem + (size_t)(y * XT_YS + xx * XT_XS) * 2 + c4 * 16) = v;
        }
    }
    __syncthreads();

    uint32_t XB = smem_to_u32(smem);
    uint32_t BB = XB + XT_BYTES;

    int yw = w >> 1;
    int xh = w & 1;

    uint32_t aoff = (uint32_t)(lane & 15) * (XT_XS * 2) +
                    (uint32_t)(lane >> 4) * 16u;
    uint32_t boff = (uint32_t)((((lane >> 4) & 1) * 8) + (lane & 7)) * SB_ROWB +
                    (uint32_t)((lane >> 3) & 1) * 16u;

    float d[2][4][4];
#pragma unroll
    for (int i = 0; i < 2; i++)
#pragma unroll
        for (int j = 0; j < 4; j++)
#pragma unroll
            for (int c = 0; c < 4; c++) d[i][j][c] = 0.0f;

    uint32_t awarp = XB + aoff + (uint32_t)yw * (XT_YS * 2) +
                     (uint32_t)xh * (32 * XT_XS * 2);
    uint32_t bwarp = BB + boff;

#pragma unroll 3
    for (int q = 0; q < 9; q++) {
        int ky = q / 3, kx = q - ky * 3;
        uint32_t aq = awarp + (uint32_t)ky * (XT_YS * 2) +
                      (uint32_t)kx * (XT_XS * 2);
        uint32_t bq = bwarp + (uint32_t)q * 64u;
#pragma unroll
        for (int h = 0; h < 2; h++) {
            uint32_t A0[4], A1[4], B0[4], B1[4];
            ldsm_x4(A0, aq + h * 32u);
            ldsm_x4(A1, aq + h * 32u + (16 * XT_XS * 2));
            ldsm_x4(B0, bq + h * 32u);
            ldsm_x4(B1, bq + h * 32u + 16u * SB_ROWB);
            mma_f16(d[0][0], A0, B0[0], B0[1]);
            mma_f16(d[0][1], A0, B0[2], B0[3]);
            mma_f16(d[0][2], A0, B1[0], B1[1]);
            mma_f16(d[0][3], A0, B1[2], B1[3]);
            mma_f16(d[1][0], A1, B0[0], B0[1]);
            mma_f16(d[1][1], A1, B0[2], B0[3]);
            mma_f16(d[1][2], A1, B1[0], B1[1]);
            mma_f16(d[1][3], A1, B1[2], B1[3]);
        }
    }

    int g  = lane >> 2;
    int tg = lane & 3;
    int yo = y0 + yw;
#pragma unroll
    for (int i = 0; i < 2; i++) {
        int xo = x0g + xh * 32 + i * 16 + g;
#pragma unroll
        for (int j = 0; j < 4; j++) {
            int co = j * 8 + tg * 2;
            float* p0 = out + (((size_t)(b * 32 + co)) * HWD + yo) * HWD + xo;
            p0[0]             = d[i][j][0];
            p0[HWD * HWD]     = d[i][j][1];
            p0[8]             = d[i][j][2];
            p0[HWD * HWD + 8] = d[i][j][3];
        }
    }
}

// ---------------------------------------------------------------------------
extern "C" void kernel_launch(void* const* d_in, const int* in_sizes, int n_in,
                              void* d_out, int out_size) {
    const float* x    = (const float*)d_in[0];
    const float* cond = (const float*)d_in[1];
    const float* W1   = (const float*)d_in[2];
    const float* b1   = (const float*)d_in[3];
    const float* W2   = (const float*)d_in[4];
    const float* b2   = (const float*)d_in[5];
    float* out = (float*)d_out;

    cudaFuncSetAttribute(conv_kernel,
                         cudaFuncAttributeMaxDynamicSharedMemorySize, CONV_SMEM);

    mlp1_kernel<<<(HIDD * NB) / 256, 256>>>(cond, W1, b1);
    fused_gemm2_xprep_kernel<<<G2_BLOCKS + NB * HWD, 128>>>(W2, b2, x);
    conv_kernel<<<dim3(2, 8, NB), 1024, CONV_SMEM>>>(out);
}

// round 17
// speedup vs baseline: 1.4043x; 1.0982x over previous
#include <cuda_runtime.h>
#include <cuda_fp16.h>
#include <cstdint>

#define NB   32
#define HWD  128
#define CONDD 256
#define HIDD 4608
#define NPARAM 9216

// Scratch (device globals: allocation-free rule)
__device__ __align__(16) __half g_hh[NB * HIDD];
#define WB_ROW   296
#define WB_ELEMS (32 * WB_ROW)              // 9472 per sample
__device__ __align__(16) __half g_wb[NB * WB_ELEMS];
// x fp16, layout [b][c4 0..3][y][x][cin8]  (32 MB)
__device__ __align__(16) __half g_xh[(size_t)NB * 4 * HWD * HWD * 8];

__device__ __forceinline__ uint32_t smem_to_u32(const void* p) {
    uint32_t a;
    asm("{ .reg .u64 t; cvta.to.shared.u64 t, %1; cvt.u32.u64 %0, t; }"
        : "=r"(a) : "l"(p));
    return a;
}

// ---------------------------------------------------------------------------
// warp-mma helpers
// ---------------------------------------------------------------------------
__device__ __forceinline__ void ldsm_x4(uint32_t r[4], uint32_t addr) {
    asm volatile("ldmatrix.sync.aligned.m8n8.x4.shared.b16 {%0,%1,%2,%3}, [%4];"
        : "=r"(r[0]), "=r"(r[1]), "=r"(r[2]), "=r"(r[3]) : "r"(addr));
}
__device__ __forceinline__ void mma_f16(float d[4], const uint32_t a[4],
                                        uint32_t b0, uint32_t b1) {
    asm volatile(
        "mma.sync.aligned.m16n8k16.row.col.f32.f16.f16.f32 "
        "{%0,%1,%2,%3}, {%4,%5,%6,%7}, {%8,%9}, {%0,%1,%2,%3};"
        : "+f"(d[0]), "+f"(d[1]), "+f"(d[2]), "+f"(d[3])
        : "r"(a[0]), "r"(a[1]), "r"(a[2]), "r"(a[3]), "r"(b0), "r"(b1));
}

// shared tile geometry (mlp1 + gemm2)
#define GP 32
#define GK 128
#define TST 272
#define SB_OFF 0                 // B tile: 32 rows
#define SA_OFF (32 * TST)        // A tile: 32 rows
#define G2_BUF (64 * TST)        // 17408 B per buffer
#define G2_SMEM (2 * G2_BUF)     // 34816 B
#define G2_BLOCKS (NPARAM / GP)  // 288

// ---------------------------------------------------------------------------
// Kernel 1: tensor-core mlp1. h[b 32, hid 4608] = relu(cond[32,256] @ W1^T + b1)
// Same fragment machinery as gemm2; A = cond, B = W1, both fp32->fp16
// converted in-register. K = 2 chunks of 128. Grid 144.
// ---------------------------------------------------------------------------
__global__ void __launch_bounds__(128, 2)
mlp1_kernel(const float* __restrict__ cond,
            const float* __restrict__ W1,
            const float* __restrict__ b1) {
    __shared__ __align__(16) unsigned char sm[G2_BUF];   // single buffer (NCH=2)

    int t = threadIdx.x, lane = t & 31, w = t >> 5;
    int pbase = blockIdx.x * GP;            // hid base

    // B (W1) load slots — identical pattern to gemm2's W2 path
    int brow = t >> 2;                      // W1 row within tile (0..31)
    int bf4  = t & 3;
    const float4* W14 = (const float4*)(W1 + (size_t)(pbase + brow) * CONDD);
    // A (cond) load slots: 32 rows x 16 groups of 8 halfs
    int arow[4], ac[4];
#pragma unroll
    for (int i = 0; i < 4; i++) {
        int j = t + 128 * i; arow[i] = j >> 4; ac[i] = j & 15;
    }

    uint32_t SMB = smem_to_u32(sm);

    int mh = w & 1;
    int nw = w >> 1;
    uint32_t Abase = SMB + SA_OFF +
        (uint32_t)(mh * 16 + (lane & 15)) * TST + (uint32_t)(lane >> 4) * 16u;
    uint32_t Bbase = SMB + SB_OFF +
        (uint32_t)(nw * 16 + (((lane >> 4) & 1) * 8) + (lane & 7)) * TST +
        (uint32_t)((lane >> 3) & 1) * 16u;

    float d0[4] = {0, 0, 0, 0}, d1[4] = {0, 0, 0, 0};

    for (int kc = 0; kc < CONDD / GK; kc++) {       // 2 chunks
        int kh = kc * GK;
        // load + convert W1 chunk
        float4 rw[8];
#pragma unroll
        for (int i = 0; i < 8; i++) rw[i] = W14[kc * 32 + bf4 + 4 * i];
        // load + convert cond chunk
        float4 ra[4][2];
#pragma unroll
        for (int i = 0; i < 4; i++) {
            const float4* c4 = (const float4*)(cond + (size_t)arow[i] * CONDD + kh);
            ra[i][0] = c4[ac[i] * 2];
            ra[i][1] = c4[ac[i] * 2 + 1];
        }
        __syncthreads();
#pragma unroll
        for (int i = 0; i < 8; i++) {
            __half2 h0 = __floats2half2_rn(rw[i].x, rw[i].y);
            __half2 h1 = __floats2half2_rn(rw[i].z, rw[i].w);
            uint32_t u0 = *(uint32_t*)&h0, u1 = *(uint32_t*)&h1;
            uint32_t addr = SMB + SB_OFF + (uint32_t)brow * TST +
                            (uint32_t)(bf4 + 4 * i) * 8u;
            asm volatile("st.shared.v2.b32 [%0], {%1, %2};"
                         :: "r"(addr), "r"(u0), "r"(u1) : "memory");
        }
#pragma unroll
        for (int i = 0; i < 4; i++) {
            __half2 h0 = __floats2half2_rn(ra[i][0].x, ra[i][0].y);
            __half2 h1 = __floats2half2_rn(ra[i][0].z, ra[i][0].w);
            __half2 h2 = __floats2half2_rn(ra[i][1].x, ra[i][1].y);
            __half2 h3 = __floats2half2_rn(ra[i][1].z, ra[i][1].w);
            uint32_t a0 = SMB + SA_OFF + (uint32_t)arow[i] * TST + ac[i] * 16u;
            asm volatile("st.shared.v4.b32 [%0], {%1, %2, %3, %4};"
                :: "r"(a0), "r"(*(uint32_t*)&h0), "r"(*(uint32_t*)&h1),
                   "r"(*(uint32_t*)&h2), "r"(*(uint32_t*)&h3) : "memory");
        }
        __syncthreads();
#pragma unroll
        for (int ks = 0; ks < 8; ks++) {
            uint32_t A[4], B[4];
            ldsm_x4(A, Abase + (uint32_t)ks * 32u);
            ldsm_x4(B, Bbase + (uint32_t)ks * 32u);
            mma_f16(d0, A, B[0], B[1]);
            mma_f16(d1, A, B[2], B[3]);
        }
        __syncthreads();
    }

    // epilogue: bias + relu -> g_hh[b][hid] fp16
    int g  = lane >> 2;
    int tg = lane & 3;
#pragma unroll
    for (int j = 0; j < 2; j++) {
        const float* dj = (j == 0) ? d0 : d1;
#pragma unroll
        for (int c = 0; c < 2; c++) {
            int p = pbase + nw * 16 + j * 8 + tg * 2 + c;   // hid
            float bias = b1[p];
            int b0 = mh * 16 + g;
            g_hh[(size_t)b0 * HIDD + p] =
                __float2half_rn(fmaxf(dj[c] + bias, 0.0f));
            g_hh[(size_t)(b0 + 8) * HIDD + p] =
                __float2half_rn(fmaxf(dj[2 + c] + bias, 0.0f));
        }
    }
}

// ---------------------------------------------------------------------------
// Kernel 2 (FUSED): blocks [0,288) = tensor-core gemm2 (double-buffered);
// blocks [288, 288+4096) = xprep (x fp32 -> g_xh fp16). Unchanged.
// ---------------------------------------------------------------------------
__global__ void __launch_bounds__(128, 2)
fused_gemm2_xprep_kernel(const float* __restrict__ W2,
                         const float* __restrict__ b2,
                         const float* __restrict__ x) {
    // ---------------- xprep path ----------------
    if (blockIdx.x >= G2_BLOCKS) {
        int bid = blockIdx.x - G2_BLOCKS;      // 0..4095
        int b = bid >> 7;                      // sample
        int y = bid & 127;                     // row
        int xx = threadIdx.x;                  // 0..127
#pragma unroll
        for (int c4 = 0; c4 < 4; c4++) {
            float v[8];
#pragma unroll
            for (int i = 0; i < 8; i++)
                v[i] = x[(((size_t)b * 32 + c4 * 8 + i) * HWD + y) * HWD + xx];
            __half2 h[4];
#pragma unroll
            for (int i = 0; i < 4; i++)
                h[i] = __floats2half2_rn(v[2 * i], v[2 * i + 1]);
            uint4 o = make_uint4(*(uint32_t*)&h[0], *(uint32_t*)&h[1],
                                 *(uint32_t*)&h[2], *(uint32_t*)&h[3]);
            *(uint4*)(g_xh + ((((size_t)b * 4 + c4) * HWD + y) * HWD + xx) * 8) = o;
        }
        return;
    }

    // ---------------- gemm2 path ----------------
    __shared__ __align__(16) unsigned char sm[G2_SMEM];

    int t = threadIdx.x, lane = t & 31, w = t >> 5;
    int pbase = blockIdx.x * GP;
    const int NCH = HIDD / GK;       // 36 chunks

    int brow = t >> 2;
    int bf4  = t & 3;
    const float4* W24 = (const float4*)(W2 + (size_t)(pbase + brow) * HIDD);
    int arow[4], ac[4];
#pragma unroll
    for (int i = 0; i < 4; i++) {
        int j = t + 128 * i; arow[i] = j >> 4; ac[i] = j & 15;
    }

    uint32_t SMB = smem_to_u32(sm);

    float4 rw[8]; uint4 rh[4];
    auto load_chunk = [&](int kc) {
        int ko = kc * 32;
#pragma unroll
        for (int i = 0; i < 8; i++) rw[i] = W24[ko + bf4 + 4 * i];
        int kh = kc * GK;
#pragma unroll
        for (int i = 0; i < 4; i++)
            rh[i] = *(const uint4*)(g_hh + (size_t)arow[i] * HIDD + kh + ac[i] * 8);
    };
    auto store_tiles = [&](uint32_t bofs) {
#pragma unroll
        for (int i = 0; i < 8; i++) {
            __half2 h0 = __floats2half2_rn(rw[i].x, rw[i].y);
            __half2 h1 = __floats2half2_rn(rw[i].z, rw[i].w);
            uint32_t u0 = *(uint32_t*)&h0, u1 = *(uint32_t*)&h1;
            uint32_t addr = SMB + bofs + SB_OFF + (uint32_t)brow * TST +
                            (uint32_t)(bf4 + 4 * i) * 8u;
            asm volatile("st.shared.v2.b32 [%0], {%1, %2};"
                         :: "r"(addr), "r"(u0), "r"(u1) : "memory");
        }
#pragma unroll
        for (int i = 0; i < 4; i++) {
            uint32_t a0 = SMB + bofs + SA_OFF + (uint32_t)arow[i] * TST + ac[i] * 16u;
            asm volatile("st.shared.v4.b32 [%0], {%1, %2, %3, %4};"
                :: "r"(a0), "r"(rh[i].x), "r"(rh[i].y), "r"(rh[i].z), "r"(rh[i].w) : "memory");
        }
    };

    int mh = w & 1;
    int nw = w >> 1;
    uint32_t Abase = SA_OFF +
        (uint32_t)(mh * 16 + (lane & 15)) * TST + (uint32_t)(lane >> 4) * 16u;
    uint32_t Bbase = SB_OFF +
        (uint32_t)(nw * 16 + (((lane >> 4) & 1) * 8) + (lane & 7)) * TST +
        (uint32_t)((lane >> 3) & 1) * 16u;

    float d0[4] = {0, 0, 0, 0}, d1[4] = {0, 0, 0, 0};

    load_chunk(0);
    store_tiles(0);
    load_chunk(1);
    __syncthreads();

    for (int kc = 0; kc < NCH; kc++) {
        uint32_t cur = (uint32_t)(kc & 1) * G2_BUF;
        if (kc + 1 < NCH) {
            store_tiles(G2_BUF - cur);
            if (kc + 2 < NCH) load_chunk(kc + 2);
        }
        __syncthreads();
#pragma unroll
        for (int ks = 0; ks < 8; ks++) {
            uint32_t A[4], B[4];
            ldsm_x4(A, SMB + cur + Abase + (uint32_t)ks * 32u);
            ldsm_x4(B, SMB + cur + Bbase + (uint32_t)ks * 32u);
            mma_f16(d0, A, B[0], B[1]);
            mma_f16(d1, A, B[2], B[3]);
        }
        __syncthreads();
    }

    int g  = lane >> 2;
    int tg = lane & 3;
#pragma unroll
    for (int j = 0; j < 2; j++) {
        const float* dj = (j == 0) ? d0 : d1;
#pragma unroll
        for (int c = 0; c < 2; c++) {
            int p = pbase + nw * 16 + j * 8 + tg * 2 + c;
            float bias = b2[p];
            int co = p / 288;
            int r  = p - co * 288;
            int cin = r / 9;
            int rr  = r - cin * 9;
            int k   = rr * 32 + cin;
            int b0 = mh * 16 + g;
            g_wb[(size_t)b0 * WB_ELEMS + co * WB_ROW + k] =
                __float2half_rn(dj[c] + bias);
            g_wb[(size_t)(b0 + 8) * WB_ELEMS + co * WB_ROW + k] =
                __float2half_rn(dj[2 + c] + bias);
        }
    }
}

// ---------------------------------------------------------------------------
// Kernel 3: warp-mma conv, fp16 — unchanged (measured 49.6 us).
// ---------------------------------------------------------------------------
#define XT_XS 40
#define XT_YS (66 * XT_XS)
#define XT_ROWS 18
#define XT_ELEMS (XT_ROWS * XT_YS)
#define XT_BYTES (XT_ELEMS * 2)  // 95040 B
#define SB_ROWB (WB_ROW * 2)     // 592 B per co row
#define SB_BYTES (32 * SB_ROWB)  // 18944 B
#define CONV_SMEM (XT_BYTES + SB_BYTES)   // 113984 B

__global__ void __launch_bounds__(1024, 1)
conv_kernel(float* __restrict__ out) {
    extern __shared__ unsigned char smem[];
    uint4* s_b4 = (uint4*)(smem + XT_BYTES);

    int t = threadIdx.x, lane = t & 31, w = t >> 5;
    int b   = blockIdx.z;
    int y0  = blockIdx.y * 16;
    int x0g = blockIdx.x * 64;

    {
        const uint4* src = (const uint4*)(g_wb + (size_t)b * WB_ELEMS);
        for (int i = t; i < SB_BYTES / 16; i += 1024) s_b4[i] = src[i];
    }
    {
        const __half* xsrc = g_xh + (size_t)b * (4 * HWD * HWD * 8);
        for (int idx = t; idx < XT_ROWS * 66 * 4; idx += 1024) {
            int row = idx >> 2, c4 = idx & 3;
            int y  = row / 66, xx = row - y * 66;
            int gy = y0 - 1 + y, gx = x0g - 1 + xx;
            uint4 v = make_uint4(0, 0, 0, 0);
            if (gy >= 0 && gy < HWD && gx >= 0 && gx < HWD)
                v = *(const uint4*)(xsrc + (((size_t)c4 * HWD + gy) * HWD + gx) * 8);
            *(uint4*)(smem + (size_t)(y * XT_YS + xx * XT_XS) * 2 + c4 * 16) = v;
        }
    }
    __syncthreads();

    uint32_t XB = smem_to_u32(smem);
    uint32_t BB = XB + XT_BYTES;

    int yw = w >> 1;
    int xh = w & 1;

    uint32_t aoff = (uint32_t)(lane & 15) * (XT_XS * 2) +
                    (uint32_t)(lane >> 4) * 16u;
    uint32_t boff = (uint32_t)((((lane >> 4) & 1) * 8) + (lane & 7)) * SB_ROWB +
                    (uint32_t)((lane >> 3) & 1) * 16u;

    float d[2][4][4];
#pragma unroll
    for (int i = 0; i < 2; i++)
#pragma unroll
        for (int j = 0; j < 4; j++)
#pragma unroll
            for (int c = 0; c < 4; c++) d[i][j][c] = 0.0f;

    uint32_t awarp = XB + aoff + (uint32_t)yw * (XT_YS * 2) +
                     (uint32_t)xh * (32 * XT_XS * 2);
    uint32_t bwarp = BB + boff;

#pragma unroll 3
    for (int q = 0; q < 9; q++) {
        int ky = q / 3, kx = q - ky * 3;
        uint32_t aq = awarp + (uint32_t)ky * (XT_YS * 2) +
                      (uint32_t)kx * (XT_XS * 2);
        uint32_t bq = bwarp + (uint32_t)q * 64u;
#pragma unroll
        for (int h = 0; h < 2; h++) {
            uint32_t A0[4], A1[4], B0[4], B1[4];
            ldsm_x4(A0, aq + h * 32u);
            ldsm_x4(A1, aq + h * 32u + (16 * XT_XS * 2));
            ldsm_x4(B0, bq + h * 32u);
            ldsm_x4(B1, bq + h * 32u + 16u * SB_ROWB);
            mma_f16(d[0][0], A0, B0[0], B0[1]);
            mma_f16(d[0][1], A0, B0[2], B0[3]);
            mma_f16(d[0][2], A0, B1[0], B1[1]);
            mma_f16(d[0][3], A0, B1[2], B1[3]);
            mma_f16(d[1][0], A1, B0[0], B0[1]);
            mma_f16(d[1][1], A1, B0[2], B0[3]);
            mma_f16(d[1][2], A1, B1[0], B1[1]);
            mma_f16(d[1][3], A1, B1[2], B1[3]);
        }
    }

    int g  = lane >> 2;
    int tg = lane & 3;
    int yo = y0 + yw;
#pragma unroll
    for (int i = 0; i < 2; i++) {
        int xo = x0g + xh * 32 + i * 16 + g;
#pragma unroll
        for (int j = 0; j < 4; j++) {
            int co = j * 8 + tg * 2;
            float* p0 = out + (((size_t)(b * 32 + co)) * HWD + yo) * HWD + xo;
            p0[0]             = d[i][j][0];
            p0[HWD * HWD]     = d[i][j][1];
            p0[8]             = d[i][j][2];
            p0[HWD * HWD + 8] = d[i][j][3];
        }
    }
}

// ---------------------------------------------------------------------------
extern "C" void kernel_launch(void* const* d_in, const int* in_sizes, int n_in,
                              void* d_out, int out_size) {
    const float* x    = (const float*)d_in[0];
    const float* cond = (const float*)d_in[1];
    const float* W1   = (const float*)d_in[2];
    const float* b1   = (const float*)d_in[3];
    const float* W2   = (const float*)d_in[4];
    const float* b2   = (const float*)d_in[5];
    float* out = (float*)d_out;

    cudaFuncSetAttribute(conv_kernel,
                         cudaFuncAttributeMaxDynamicSharedMemorySize, CONV_SMEM);

    mlp1_kernel<<<HIDD / GP, 128>>>(cond, W1, b1);
    fused_gemm2_xprep_kernel<<<G2_BLOCKS + NB * HWD, 128>>>(W2, b2, x);
    conv_kernel<<<dim3(2, 8, NB), 1024, CONV_SMEM>>>(out);
}